// round 10
// baseline (speedup 1.0000x reference)
#include <cuda_runtime.h>

// Dykstra alternating projection, n=4096, up to 20 iterations.
//   Xp = X + (1/n + s/n^2) - row_i/n - col_j/n ;  X <- relu(Xp)
//   freeze X once min(Xp) >= 0  (relu(Xp)==Xp in that case)
//
// R9 -> R10: occupancy attack. R9 post-mortem showed time ~ 1/occupancy
// (regs 64->76 dropped occ 36->32% and slowed it down). Column-split the
// grid 4x (2048 blocks, 8 rows x 1024 cols per block, 1 float4/thread/row)
// so register state shrinks to ~16 accumulators; __launch_bounds__(256,6)
// targets 48 warps/SM (vs ~28). Row sums become cross-block partials ->
// triple-buffered g_row with atomicAdd, same trick as cols.

#define NDIM 4096
#define RPB 8                          // rows per block
#define CS 4                           // column segments
#define NBLK ((NDIM / RPB) * CS)       // 2048 blocks
#define NTHREADS 256
#define NWARPS (NTHREADS / 32)         // 8
#define MAXIT 20
#define F4_PER_ROW (NDIM / 4)          // 1024 float4 per row
#define F4_PER_SEG (F4_PER_ROW / CS)   // 256 = NTHREADS -> 1 f4/thread/row
#define ROW_F4 (NDIM / 4)              // g_row viewed as 1024 float4

__device__ float4 g_col[3][F4_PER_ROW];   // col sums, triple-buffered
__device__ float4 g_rowb[3][ROW_F4];      // row sums, triple-buffered (as f4)
__device__ float  g_total[MAXIT + 1];     // per-iteration totals
__device__ int    g_neg[MAXIT];           // any-negative flag per iteration

__global__ void init_kernel() {
    int t = threadIdx.x;
    float4 z = make_float4(0.f, 0.f, 0.f, 0.f);
    for (int i = t; i < F4_PER_ROW; i += NTHREADS) {
        g_col[0][i] = z; g_col[1][i] = z;
        g_rowb[0][i] = z; g_rowb[1][i] = z;
    }
    if (t <= MAXIT) g_total[t] = 0.f;
    if (t < MAXIT)  g_neg[t] = 0;
}

__device__ __forceinline__ float warpReduceSum(float v) {
    #pragma unroll
    for (int o = 16; o > 0; o >>= 1) v += __shfl_down_sync(0xffffffffu, v, o);
    return v;
}

// Pre-pass: row/col/total sums of the initial X (input for iteration 0).
__global__ __launch_bounds__(NTHREADS, 6)
void reduce0_kernel(const float* __restrict__ X) {
    __shared__ float s_part[NWARPS][RPB];
    __shared__ float s_rs[RPB];
    int t = threadIdx.x;
    int lane = t & 31, wid = t >> 5;
    int rg = blockIdx.x >> 2, cs = blockIdx.x & 3;
    int row0 = rg * RPB;
    int col4 = cs * F4_PER_SEG + t;    // this thread's f4 index within a row

    float4 cacc = make_float4(0.f, 0.f, 0.f, 0.f);
    float rp[RPB];
    #pragma unroll
    for (int r = 0; r < RPB; r++) rp[r] = 0.f;

    const float4* Xf4 = (const float4*)X;
    #pragma unroll
    for (int r = 0; r < RPB; r++) {
        float4 v = Xf4[(size_t)(row0 + r) * F4_PER_ROW + col4];
        rp[r] = (v.x + v.y) + (v.z + v.w);
        cacc.x += v.x; cacc.y += v.y; cacc.z += v.z; cacc.w += v.w;
    }

    #pragma unroll
    for (int r = 0; r < RPB; r++) {
        float v = warpReduceSum(rp[r]);
        if (lane == 0) s_part[wid][r] = v;
    }
    // col partials (independent of barriers)
    float* gc = (float*)&g_col[0][col4];
    atomicAdd(gc + 0, cacc.x); atomicAdd(gc + 1, cacc.y);
    atomicAdd(gc + 2, cacc.z); atomicAdd(gc + 3, cacc.w);

    __syncthreads();
    if (t < RPB) {
        float rs = 0.f;
        #pragma unroll
        for (int w = 0; w < NWARPS; w++) rs += s_part[w][t];
        atomicAdd(&((float*)g_rowb[0])[row0 + t], rs);
        s_rs[t] = rs;
    }
    __syncthreads();
    if (t == 0) {
        float bt = 0.f;
        #pragma unroll
        for (int r = 0; r < RPB; r++) bt += s_rs[r];
        atomicAdd(&g_total[0], bt);
    }
}

// Iteration k: update X (in place after k=0) + reductions for iteration k+1.
__global__ __launch_bounds__(NTHREADS, 6)
void fused_kernel(const float* __restrict__ Xin, float* __restrict__ Xout,
                  int k, const int* __restrict__ max_iters) {
    __shared__ float s_part[NWARPS][RPB];
    __shared__ float s_rs[RPB];
    __shared__ float s_rowsub[RPB];
    __shared__ int s_done;
    int t = threadIdx.x;
    int lane = t & 31, wid = t >> 5;
    int rg = blockIdx.x >> 2, cs = blockIdx.x & 3;
    int row0 = rg * RPB;
    int col4 = cs * F4_PER_SEG + t;

    const float inv_n = 1.0f / NDIM;
    int rdc = k % 3, wrc = (k + 1) % 3, zc = (k + 2) % 3;

    // Parallel done-check (one warp) while another warp fetches row subtractors.
    if (t < 32) {
        int z = (t < k) ? (g_neg[t] == 0) : 0;
        unsigned m = __ballot_sync(0xffffffffu, z);
        if (t == 0) s_done = (m != 0u) || (k >= *max_iters);
    }
    if (t >= 32 && t < 32 + RPB)
        s_rowsub[t - 32] = ((const float*)g_rowb[rdc])[row0 + (t - 32)] * inv_n;
    __syncthreads();

    if (s_done) {
        if (k == 0) {  // max_iters==0: output = input (never hit for 20)
            const float4* xi = (const float4*)Xin;
            float4*       yo = (float4*)Xout;
            #pragma unroll
            for (int r = 0; r < RPB; r++)
                yo[(size_t)(row0 + r) * F4_PER_ROW + col4] =
                    xi[(size_t)(row0 + r) * F4_PER_ROW + col4];
        }
        return;
    }

    float total = g_total[k];                 // uniform load, L2 broadcast
    float c = inv_n + total * inv_n * inv_n;

    // Zero buffers iteration k+1 accumulates into (dead since k-1).
    // 2048 f4 words to zero across 2048 blocks -> 1 per block.
    {
        int b = blockIdx.x;
        float4 z = make_float4(0.f, 0.f, 0.f, 0.f);
        if (b < F4_PER_ROW) g_col[zc][b] = z;
        else                g_rowb[zc][b - F4_PER_ROW] = z;
    }

    // This thread's col values (pre-scaled), reused across all RPB rows.
    float4 cv = g_col[rdc][col4];
    float4 cvn = make_float4(cv.x * inv_n, cv.y * inv_n, cv.z * inv_n, cv.w * inv_n);

    float4 cacc = make_float4(0.f, 0.f, 0.f, 0.f);
    float rp[RPB];
    bool neg = false;

    const float4* xi = (const float4*)Xin;
    float4*       yo = (float4*)Xout;

    #pragma unroll
    for (int r = 0; r < RPB; r++) {
        size_t i = (size_t)(row0 + r) * F4_PER_ROW + col4;
        float4 v = xi[i];
        float a = c - s_rowsub[r];
        float4 xp;
        xp.x = v.x + a - cvn.x;
        xp.y = v.y + a - cvn.y;
        xp.z = v.z + a - cvn.z;
        xp.w = v.w + a - cvn.w;
        float mn = fminf(fminf(xp.x, xp.y), fminf(xp.z, xp.w));
        neg = neg || (mn < 0.f);
        float4 y;
        y.x = fmaxf(xp.x, 0.f); y.y = fmaxf(xp.y, 0.f);
        y.z = fmaxf(xp.z, 0.f); y.w = fmaxf(xp.w, 0.f);
        yo[i] = y;
        rp[r] = (y.x + y.y) + (y.z + y.w);
        cacc.x += y.x; cacc.y += y.y; cacc.z += y.z; cacc.w += y.w;
    }

    // Row partials: warp-level, barrier-free.
    #pragma unroll
    for (int r = 0; r < RPB; r++) {
        float v = warpReduceSum(rp[r]);
        if (lane == 0) s_part[wid][r] = v;
    }

    // Col partials (REDG, fire-and-forget).
    float* gc = (float*)&g_col[wrc][col4];
    atomicAdd(gc + 0, cacc.x); atomicAdd(gc + 1, cacc.y);
    atomicAdd(gc + 2, cacc.z); atomicAdd(gc + 3, cacc.w);

    // Neg flag: one store per warp that saw a negative.
    if (__any_sync(0xffffffffu, neg)) {
        if (lane == 0) g_neg[k] = 1;
    }

    __syncthreads();
    if (t < RPB) {
        float rs = 0.f;
        #pragma unroll
        for (int w = 0; w < NWARPS; w++) rs += s_part[w][t];
        atomicAdd(&((float*)g_rowb[wrc])[row0 + t], rs);
        s_rs[t] = rs;
    }
    __syncthreads();
    if (t == 0) {
        float bt = 0.f;
        #pragma unroll
        for (int r = 0; r < RPB; r++) bt += s_rs[r];
        atomicAdd(&g_total[k + 1], bt);
    }
}

extern "C" void kernel_launch(void* const* d_in, const int* in_sizes, int n_in,
                              void* d_out, int out_size) {
    const float* X = (const float*)d_in[0];
    const int* max_iters = (const int*)d_in[1];
    float* out = (float*)d_out;
    (void)in_sizes; (void)n_in; (void)out_size;

    init_kernel<<<1, NTHREADS>>>();
    reduce0_kernel<<<NBLK, NTHREADS>>>(X);
    for (int k = 0; k < MAXIT; k++) {
        const float* src = (k == 0) ? X : out;
        fused_kernel<<<NBLK, NTHREADS>>>(src, out, k, max_iters);
    }
}

// round 11
// speedup vs baseline: 1.7057x; 1.7057x over previous
#include <cuda_runtime.h>

// Dykstra alternating projection, n=4096, up to 20 iterations.
//   Xp = X + (1/n + s/n^2) - row_i/n - col_j/n ;  X <- relu(Xp)
//   freeze X once min(Xp) >= 0  (relu(Xp)==Xp in that case)
//
// R10 -> R11: in-flight-bytes attack. R9 (high MLP, grid-capped occ) and
// R10 (high occ, reg-capped MLP) both lost; the governing product is
// warps/SM x per-thread MLP. This version: grid=1024 (16 rows x 256 f4-cols
// per block), explicit software pipeline of depth 8 on the row loads
// (buf[8] float4 = 32 regs), launch_bounds(256,4) -> 32 warps/SM with
// MLP ~8 -> ~4KB in flight per SM (2.3x R8). Row sums shuffle-reduced
// in-loop (no rp[] array), col atomics halved via 16-row accumulation.

#define NDIM 4096
#define RPB 16                         // rows per block
#define CS 4                           // column segments
#define NBLK ((NDIM / RPB) * CS)       // 1024 blocks
#define NTHREADS 256
#define NWARPS (NTHREADS / 32)         // 8
#define MAXIT 20
#define F4_PER_ROW (NDIM / 4)          // 1024 float4 per row
#define F4_PER_SEG (F4_PER_ROW / CS)   // 256 = NTHREADS -> 1 f4/thread/row
#define PIPE 8                         // load pipeline depth (rows)

__device__ float4 g_col[3][F4_PER_ROW];   // col sums, triple-buffered
__device__ float4 g_rowb[3][F4_PER_ROW];  // row sums (4096 floats), triple-buffered
__device__ float  g_total[MAXIT + 1];     // per-iteration totals
__device__ int    g_neg[MAXIT];           // any-negative flag per iteration

__global__ void init_kernel() {
    int t = threadIdx.x;
    float4 z = make_float4(0.f, 0.f, 0.f, 0.f);
    for (int i = t; i < F4_PER_ROW; i += NTHREADS) {
        g_col[0][i] = z; g_col[1][i] = z;
        g_rowb[0][i] = z; g_rowb[1][i] = z;
    }
    if (t <= MAXIT) g_total[t] = 0.f;
    if (t < MAXIT)  g_neg[t] = 0;
}

__device__ __forceinline__ float warpReduceSum(float v) {
    #pragma unroll
    for (int o = 16; o > 0; o >>= 1) v += __shfl_down_sync(0xffffffffu, v, o);
    return v;
}

// Pre-pass: row/col/total sums of the initial X (input for iteration 0).
__global__ __launch_bounds__(NTHREADS, 4)
void reduce0_kernel(const float* __restrict__ X) {
    __shared__ float s_part[NWARPS][RPB];
    __shared__ float s_rs[RPB];
    int t = threadIdx.x;
    int lane = t & 31, wid = t >> 5;
    int rg = blockIdx.x >> 2, cseg = blockIdx.x & 3;
    int row0 = rg * RPB;
    int col4 = cseg * F4_PER_SEG + t;

    const float4* xi = (const float4*)X;
    size_t base = (size_t)row0 * F4_PER_ROW + col4;

    float4 cacc = make_float4(0.f, 0.f, 0.f, 0.f);
    float4 buf[PIPE];
    #pragma unroll
    for (int r = 0; r < PIPE; r++) buf[r] = xi[base + (size_t)r * F4_PER_ROW];

    #pragma unroll
    for (int r = 0; r < RPB; r++) {
        float4 v = buf[r & (PIPE - 1)];
        if (r + PIPE < RPB)
            buf[r & (PIPE - 1)] = xi[base + (size_t)(r + PIPE) * F4_PER_ROW];
        cacc.x += v.x; cacc.y += v.y; cacc.z += v.z; cacc.w += v.w;
        float rs = warpReduceSum((v.x + v.y) + (v.z + v.w));
        if (lane == 0) s_part[wid][r] = rs;
    }

    float* gc = (float*)&g_col[0][col4];
    atomicAdd(gc + 0, cacc.x); atomicAdd(gc + 1, cacc.y);
    atomicAdd(gc + 2, cacc.z); atomicAdd(gc + 3, cacc.w);

    __syncthreads();
    if (t < RPB) {
        float rs = 0.f;
        #pragma unroll
        for (int w = 0; w < NWARPS; w++) rs += s_part[w][t];
        atomicAdd(&((float*)g_rowb[0])[row0 + t], rs);
        s_rs[t] = rs;
    }
    __syncthreads();
    if (t == 0) {
        float bt = 0.f;
        #pragma unroll
        for (int r = 0; r < RPB; r++) bt += s_rs[r];
        atomicAdd(&g_total[0], bt);
    }
}

// Iteration k: update X (in place after k=0) + reductions for iteration k+1.
__global__ __launch_bounds__(NTHREADS, 4)
void fused_kernel(const float* __restrict__ Xin, float* __restrict__ Xout,
                  int k, const int* __restrict__ max_iters) {
    __shared__ float s_part[NWARPS][RPB];
    __shared__ float s_rs[RPB];
    __shared__ float s_rowsub[RPB];
    __shared__ int s_done;
    int t = threadIdx.x;
    int lane = t & 31, wid = t >> 5;
    int rg = blockIdx.x >> 2, cseg = blockIdx.x & 3;
    int row0 = rg * RPB;
    int col4 = cseg * F4_PER_SEG + t;

    const float inv_n = 1.0f / NDIM;
    int rdc = k % 3, wrc = (k + 1) % 3, zc = (k + 2) % 3;

    // Done-check (warp 0) while warp 1 fetches the 16 row subtractors.
    if (t < 32) {
        int z = (t < k) ? (g_neg[t] == 0) : 0;
        unsigned m = __ballot_sync(0xffffffffu, z);
        if (t == 0) s_done = (m != 0u) || (k >= *max_iters);
    }
    if (t >= 32 && t < 32 + RPB)
        s_rowsub[t - 32] = ((const float*)g_rowb[rdc])[row0 + (t - 32)] * inv_n;
    __syncthreads();

    const float4* xi = (const float4*)Xin;
    float4*       yo = (float4*)Xout;
    size_t base = (size_t)row0 * F4_PER_ROW + col4;

    if (s_done) {
        if (k == 0) {  // max_iters==0: output = input (never hit for 20)
            #pragma unroll
            for (int r = 0; r < RPB; r++)
                yo[base + (size_t)r * F4_PER_ROW] = xi[base + (size_t)r * F4_PER_ROW];
        }
        return;
    }

    float total = g_total[k];
    float c = inv_n + total * inv_n * inv_n;

    // Zero the buffers iteration k+1 accumulates into (dead since k-1):
    // 2048 f4 words over 1024 blocks -> 2 per block.
    {
        float4 z = make_float4(0.f, 0.f, 0.f, 0.f);
        int b = blockIdx.x;
        if (b < 512) { g_col[zc][2 * b] = z;  g_col[zc][2 * b + 1] = z; }
        else { int i = 2 * (b - 512); g_rowb[zc][i] = z; g_rowb[zc][i + 1] = z; }
    }

    // This thread's col values (pre-scaled), reused across all 16 rows.
    float4 cv = g_col[rdc][col4];
    float4 cvn = make_float4(cv.x * inv_n, cv.y * inv_n, cv.z * inv_n, cv.w * inv_n);

    float4 cacc = make_float4(0.f, 0.f, 0.f, 0.f);
    bool neg = false;

    // Software-pipelined row loop: loads for row r+PIPE in flight while
    // computing row r -> per-thread MLP ~PIPE.
    float4 buf[PIPE];
    #pragma unroll
    for (int r = 0; r < PIPE; r++) buf[r] = xi[base + (size_t)r * F4_PER_ROW];

    #pragma unroll
    for (int r = 0; r < RPB; r++) {
        float4 v = buf[r & (PIPE - 1)];
        if (r + PIPE < RPB)
            buf[r & (PIPE - 1)] = xi[base + (size_t)(r + PIPE) * F4_PER_ROW];
        float a = c - s_rowsub[r];
        float4 xp;
        xp.x = v.x + a - cvn.x;
        xp.y = v.y + a - cvn.y;
        xp.z = v.z + a - cvn.z;
        xp.w = v.w + a - cvn.w;
        float mn = fminf(fminf(xp.x, xp.y), fminf(xp.z, xp.w));
        neg = neg || (mn < 0.f);
        float4 y;
        y.x = fmaxf(xp.x, 0.f); y.y = fmaxf(xp.y, 0.f);
        y.z = fmaxf(xp.z, 0.f); y.w = fmaxf(xp.w, 0.f);
        yo[base + (size_t)r * F4_PER_ROW] = y;
        cacc.x += y.x; cacc.y += y.y; cacc.z += y.z; cacc.w += y.w;
        float rs = warpReduceSum((y.x + y.y) + (y.z + y.w));
        if (lane == 0) s_part[wid][r] = rs;
    }

    // Col partials (REDG, fire-and-forget).
    float* gc = (float*)&g_col[wrc][col4];
    atomicAdd(gc + 0, cacc.x); atomicAdd(gc + 1, cacc.y);
    atomicAdd(gc + 2, cacc.z); atomicAdd(gc + 3, cacc.w);

    // Neg flag: one store per warp that saw a negative.
    if (__any_sync(0xffffffffu, neg)) {
        if (lane == 0) g_neg[k] = 1;
    }

    __syncthreads();
    if (t < RPB) {
        float rs = 0.f;
        #pragma unroll
        for (int w = 0; w < NWARPS; w++) rs += s_part[w][t];
        atomicAdd(&((float*)g_rowb[wrc])[row0 + t], rs);
        s_rs[t] = rs;
    }
    __syncthreads();
    if (t == 0) {
        float bt = 0.f;
        #pragma unroll
        for (int r = 0; r < RPB; r++) bt += s_rs[r];
        atomicAdd(&g_total[k + 1], bt);
    }
}

extern "C" void kernel_launch(void* const* d_in, const int* in_sizes, int n_in,
                              void* d_out, int out_size) {
    const float* X = (const float*)d_in[0];
    const int* max_iters = (const int*)d_in[1];
    float* out = (float*)d_out;
    (void)in_sizes; (void)n_in; (void)out_size;

    init_kernel<<<1, NTHREADS>>>();
    reduce0_kernel<<<NBLK, NTHREADS>>>(X);
    for (int k = 0; k < MAXIT; k++) {
        const float* src = (k == 0) ? X : out;
        fused_kernel<<<NBLK, NTHREADS>>>(src, out, k, max_iters);
    }
}

// round 12
// speedup vs baseline: 4.0303x; 2.3628x over previous
#include <cuda_runtime.h>
#include <cstdint>

// Dykstra alternating projection, n=4096, up to 20 iterations.
//   Xp = X + (1/n + s/n^2) - row_i/n - col_j/n ;  X <- relu(Xp)
//   freeze X once min(Xp) >= 0  (relu(Xp)==Xp in that case)
//
// R11 -> R12: isolate the atomic path. R8 (champion, 40.6us/kernel) is kept
// structurally identical; the ONLY change is col-sum accumulation:
// 4096 scalar atomicAdds per block -> SMEM staging (16KB) + a single
// cp.reduce.async.bulk (TMA-pipe bulk f32 add into g_col). Occupancy/MLP
// sweeps (R9/R10/R11) all failed; suspect 2.1M LSU atomics/iter are the
// shared serialization floor.

#define NDIM 4096
#define RPB 8                         // rows per block
#define NBLK (NDIM / RPB)             // 512 blocks
#define NTHREADS 256
#define MAXIT 20
#define F4_PER_ROW (NDIM / 4)         // 1024 float4 per row
#define F4_PER_THREAD (F4_PER_ROW / NTHREADS) // 4
#define F4_ZERO_PER_BLK (F4_PER_ROW / NBLK)   // 2
#define COL_BYTES (NDIM * 4)          // 16384 bytes of col partials

__device__ float  g_row[NDIM];              // row sums (exclusive per block)
__device__ float4 g_col[3][F4_PER_ROW];     // col sums, triple-buffered
__device__ float  g_total[MAXIT + 1];       // per-iteration totals
__device__ int    g_neg[MAXIT];             // any-negative flag per iteration

__global__ void init_kernel() {
    int t = threadIdx.x;
    for (int i = t; i < F4_PER_ROW; i += NTHREADS) {
        g_col[0][i] = make_float4(0.f, 0.f, 0.f, 0.f);
        g_col[1][i] = make_float4(0.f, 0.f, 0.f, 0.f);
    }
    if (t <= MAXIT) g_total[t] = 0.f;
    if (t < MAXIT)  g_neg[t] = 0;
}

__device__ __forceinline__ float blockReduceSum(float v) {
    __shared__ float s[NTHREADS / 32];
    #pragma unroll
    for (int o = 16; o > 0; o >>= 1) v += __shfl_down_sync(0xffffffffu, v, o);
    if ((threadIdx.x & 31) == 0) s[threadIdx.x >> 5] = v;
    __syncthreads();
    float r = 0.f;
    if (threadIdx.x < NTHREADS / 32) r = s[threadIdx.x];
    if (threadIdx.x < 32) {
        #pragma unroll
        for (int o = NTHREADS / 64; o > 0; o >>= 1)
            r += __shfl_down_sync(0xffffffffu, r, o);
    }
    __syncthreads();
    return r;  // valid on thread 0
}

// One bulk reduce-add of a 16KB SMEM buffer into gmem (async-proxy, sm_90+).
// Caller must have __syncthreads()'d after the SMEM writes.
__device__ __forceinline__ void bulk_reduce_add_f32(void* gdst, const void* smem_src) {
    if (threadIdx.x == 0) {
        asm volatile("fence.proxy.async.shared::cta;" ::: "memory");
        uint32_t saddr;
        asm volatile("{\n\t.reg .u64 t;\n\tcvta.to.shared.u64 t, %1;\n\tcvt.u32.u64 %0, t;\n\t}"
                     : "=r"(saddr) : "l"(smem_src));
        asm volatile("{\n\t.reg .u64 g;\n\tcvta.to.global.u64 g, %0;\n\t"
                     "cp.reduce.async.bulk.global.shared::cta.bulk_group.add.f32 [g], [%1], %2;\n\t}"
                     :: "l"((uint64_t)gdst), "r"(saddr), "r"((uint32_t)COL_BYTES) : "memory");
        asm volatile("cp.async.bulk.commit_group;" ::: "memory");
        asm volatile("cp.async.bulk.wait_group 0;" ::: "memory");
    }
}

// Pre-pass: row/col/total sums of the initial X (input for iteration 0).
__global__ __launch_bounds__(NTHREADS)
void reduce0_kernel(const float* __restrict__ X) {
    __shared__ __align__(16) float4 s_colpart[F4_PER_ROW];
    int t = threadIdx.x;
    int row0 = blockIdx.x * RPB;
    float4 cacc[F4_PER_THREAD];
    #pragma unroll
    for (int g = 0; g < F4_PER_THREAD; g++) cacc[g] = make_float4(0.f, 0.f, 0.f, 0.f);
    float btotal = 0.f;
    for (int r = 0; r < RPB; r++) {
        const float4* xr = (const float4*)(X + (size_t)(row0 + r) * NDIM);
        float rp = 0.f;
        #pragma unroll
        for (int g = 0; g < F4_PER_THREAD; g++) {
            float4 v = xr[t + NTHREADS * g];
            rp += (v.x + v.y) + (v.z + v.w);
            cacc[g].x += v.x; cacc[g].y += v.y; cacc[g].z += v.z; cacc[g].w += v.w;
        }
        float rs = blockReduceSum(rp);
        if (t == 0) { g_row[row0 + r] = rs; btotal += rs; }
    }
    if (t == 0) atomicAdd(&g_total[0], btotal);
    #pragma unroll
    for (int g = 0; g < F4_PER_THREAD; g++)
        s_colpart[t + NTHREADS * g] = cacc[g];
    __syncthreads();
    bulk_reduce_add_f32(&g_col[0][0], s_colpart);
}

// Iteration k: update X (in place after k=0) + reductions for iteration k+1.
__global__ __launch_bounds__(NTHREADS)
void fused_kernel(const float* __restrict__ Xin, float* __restrict__ Xout,
                  int k, const int* __restrict__ max_iters) {
    __shared__ __align__(16) float4 s_colpart[F4_PER_ROW];
    __shared__ int s_done;
    __shared__ float s_rowsub[RPB];
    int t = threadIdx.x;
    int row0 = blockIdx.x * RPB;

    // Done-check via one-warp ballot; warp 1 prefetches row subtractors.
    if (t < 32) {
        int z = (t < k) ? (g_neg[t] == 0) : 0;
        unsigned m = __ballot_sync(0xffffffffu, z);
        if (t == 0) s_done = (m != 0u) || (k >= *max_iters);
    }
    if (t >= 32 && t < 32 + RPB)
        s_rowsub[t - 32] = g_row[row0 + (t - 32)] * (1.0f / NDIM);
    __syncthreads();
    if (s_done) {
        if (k == 0) {  // max_iters==0: output = input (never hit for 20)
            for (int r = 0; r < RPB; r++) {
                const float4* xr = (const float4*)(Xin + (size_t)(row0 + r) * NDIM);
                float4*       yr = (float4*)(Xout + (size_t)(row0 + r) * NDIM);
                #pragma unroll
                for (int g = 0; g < F4_PER_THREAD; g++)
                    yr[t + NTHREADS * g] = xr[t + NTHREADS * g];
            }
        }
        return;
    }

    const float inv_n = 1.0f / NDIM;
    float total = g_total[k];
    float c = inv_n + total * inv_n * inv_n;

    int rdc = k % 3, wrc = (k + 1) % 3, zc = (k + 2) % 3;

    // Hoist this thread's col values (pre-scaled) — reused across all RPB rows.
    float4 cvn[F4_PER_THREAD];
    #pragma unroll
    for (int g = 0; g < F4_PER_THREAD; g++) {
        float4 cv = g_col[rdc][t + NTHREADS * g];
        cvn[g] = make_float4(cv.x * inv_n, cv.y * inv_n, cv.z * inv_n, cv.w * inv_n);
    }

    float4 cacc[F4_PER_THREAD];
    #pragma unroll
    for (int g = 0; g < F4_PER_THREAD; g++) cacc[g] = make_float4(0.f, 0.f, 0.f, 0.f);
    bool neg = false;
    float btotal = 0.f;

    for (int r = 0; r < RPB; r++) {
        const float4* xr = (const float4*)(Xin + (size_t)(row0 + r) * NDIM);
        float4*       yr = (float4*)(Xout + (size_t)(row0 + r) * NDIM);
        float a = c - s_rowsub[r];
        float rp = 0.f;
        #pragma unroll
        for (int g = 0; g < F4_PER_THREAD; g++) {
            int i = t + NTHREADS * g;
            float4 v = xr[i];
            float4 xp;
            xp.x = v.x + a - cvn[g].x;
            xp.y = v.y + a - cvn[g].y;
            xp.z = v.z + a - cvn[g].z;
            xp.w = v.w + a - cvn[g].w;
            neg = neg || (xp.x < 0.f) || (xp.y < 0.f) || (xp.z < 0.f) || (xp.w < 0.f);
            float4 y;
            y.x = fmaxf(xp.x, 0.f); y.y = fmaxf(xp.y, 0.f);
            y.z = fmaxf(xp.z, 0.f); y.w = fmaxf(xp.w, 0.f);
            yr[i] = y;
            rp += (y.x + y.y) + (y.z + y.w);
            cacc[g].x += y.x; cacc[g].y += y.y; cacc[g].z += y.z; cacc[g].w += y.w;
        }
        float rs = blockReduceSum(rp);
        if (t == 0) { g_row[row0 + r] = rs; btotal += rs; }
    }

    if (t == 0) atomicAdd(&g_total[k + 1], btotal);

    // Col partials: SMEM staging + one bulk reduce-add (TMA pipe, no LSU atomics).
    #pragma unroll
    for (int g = 0; g < F4_PER_THREAD; g++)
        s_colpart[t + NTHREADS * g] = cacc[g];

    if (__syncthreads_or(neg ? 1 : 0)) {
        if (t == 0) g_neg[k] = 1;
    }
    // (the syncthreads_or above also orders s_colpart writes)
    bulk_reduce_add_f32(&g_col[wrc][0], s_colpart);

    // Zero the col buffer iteration k+1 accumulates into (dead since k-1).
    if (t < F4_ZERO_PER_BLK)
        g_col[zc][blockIdx.x * F4_ZERO_PER_BLK + t] = make_float4(0.f, 0.f, 0.f, 0.f);
}

extern "C" void kernel_launch(void* const* d_in, const int* in_sizes, int n_in,
                              void* d_out, int out_size) {
    const float* X = (const float*)d_in[0];
    const int* max_iters = (const int*)d_in[1];
    float* out = (float*)d_out;
    (void)in_sizes; (void)n_in; (void)out_size;

    init_kernel<<<1, NTHREADS>>>();
    reduce0_kernel<<<NBLK, NTHREADS>>>(X);
    for (int k = 0; k < MAXIT; k++) {
        const float* src = (k == 0) ? X : out;
        fused_kernel<<<NBLK, NTHREADS>>>(src, out, k, max_iters);
    }
}